// round 13
// baseline (speedup 1.0000x reference)
#include <cuda_runtime.h>
#include <cuda_fp16.h>
#include <cstdint>

// ============================================================================
// ResAttentionBlock (ptxas target sm_103 rejects tcgen05 -> legacy mma.sync).
// R13: persistent-CTA KV kernel (grid=148, 1 CTA/SM): the 3-stage cp.async
//      ring continues ACROSS tile boundaries, so pipeline fill is paid once
//      per SM and each tile's attention epilogue overlaps the next tile's
//      chunk loads. Q kernel (+fused y conversion) unchanged from R11/12.
// ============================================================================

#define EPS 1e-6f
constexpr int NROWS = 65536;
constexpr int HID   = 1024;
constexpr int KC    = 64;              // k-chunk (elements)
constexpr int NCH   = HID / KC;        // 16
constexpr int TPAD  = 72;              // padded row stride in fp16 elems (144B)
constexpr int TILE_B = 128 * TPAD * 2; // one 128x64 fp16 tile = 18432 B
constexpr int STG   = 3;               // pipeline stages
constexpr int NTILES = (NROWS / 128) * (HID / 128);   // 4096 KV tiles
constexpr int PGRID  = 148;            // persistent grid (1 CTA/SM)

constexpr int SMEM_Q  = 512 + STG * 2 * TILE_B;    // 111104
constexpr int SMEM_KV = STG * 3 * TILE_B;          // 165888

// k_prep grid partition
constexpr int PREP_RMS  = 8192;
constexpr int PREP_W    = 3072;
constexpr int PREP_RMAP = 256;
constexpr int PREP_FLAG = 64;
constexpr int PREP_GRID = PREP_RMS + PREP_W + PREP_RMAP + PREP_FLAG;

// ---------------- scratch (device globals; no allocation allowed) -----------
__device__ __align__(16) __half g_h [67108864];
__device__ __align__(16) __half g_yb[67108864];
__device__ __align__(16) __half g_xq[67108864];
__device__ __align__(16) __half g_wq[1048576];
__device__ __align__(16) __half g_wk[1048576];
__device__ __align__(16) __half g_wv[1048576];
__device__ __align__(16) int g_list[NROWS];
__device__ __align__(16) int g_pos [NROWS];
__device__ __align__(16) int g_rep2[NROWS];
__device__ __align__(16) unsigned char g_flag[NROWS];   // BSS zero-initialized
__device__ int g_cnt[2];

// ---------------- helpers ----------------------------------------------------
__device__ __forceinline__ uint32_t smem_u32(const void* p) {
    uint32_t a;
    asm("{ .reg .u64 t; cvta.to.shared.u64 t, %1; cvt.u32.u64 %0, t; }" : "=r"(a) : "l"(p));
    return a;
}
__device__ __forceinline__ void cp_async16(uint32_t dst, const void* src) {
    asm volatile("cp.async.cg.shared.global [%0], [%1], 16;" :: "r"(dst), "l"(src) : "memory");
}
#define CP_COMMIT() asm volatile("cp.async.commit_group;" ::: "memory")
#define CP_WAIT(n)  asm volatile("cp.async.wait_group %0;" :: "n"(n) : "memory")

__device__ __forceinline__ void ldm_x4(uint32_t* r, uint32_t addr) {
    asm volatile("ldmatrix.sync.aligned.m8n8.x4.shared.b16 {%0,%1,%2,%3}, [%4];"
                 : "=r"(r[0]), "=r"(r[1]), "=r"(r[2]), "=r"(r[3]) : "r"(addr));
}
__device__ __forceinline__ void mma_h32(float* d, const uint32_t* a, const uint32_t* b) {
    asm volatile(
        "mma.sync.aligned.m16n8k16.row.col.f32.f16.f16.f32 "
        "{%0,%1,%2,%3}, {%4,%5,%6,%7}, {%8,%9}, {%0,%1,%2,%3};"
        : "+f"(d[0]), "+f"(d[1]), "+f"(d[2]), "+f"(d[3])
        : "r"(a[0]), "r"(a[1]), "r"(a[2]), "r"(a[3]), "r"(b[0]), "r"(b[1]));
}
__device__ __forceinline__ uint2 f4_to_h2x2(float4 v) {
    __half2 p0 = __floats2half2_rn(v.x, v.y);
    __half2 p1 = __floats2half2_rn(v.z, v.w);
    uint2 s;
    s.x = *reinterpret_cast<uint32_t*>(&p0);
    s.y = *reinterpret_cast<uint32_t*>(&p1);
    return s;
}

// Load one 128-row x 64-col fp16 tile into padded smem (stride 144B). 256 thr.
__device__ __forceinline__ void load_tile(uint32_t sbase, const __half* __restrict__ g,
                                          int row0, int col0) {
    const int tid = threadIdx.x;
#pragma unroll
    for (int k = 0; k < 4; k++) {
        int u = tid + k * 256;
        int r = u >> 3, c = u & 7;
        cp_async16(sbase + r * (TPAD * 2) + c * 16,
                   g + (size_t)(row0 + r) * HID + col0 + c * 8);
    }
}

// ---------------- compaction kernels -----------------------------------------
__global__ void __launch_bounds__(1024) k_mark(const int* __restrict__ rep) {
    g_flag[rep[blockIdx.x * 1024 + threadIdx.x]] = 1;
}
__global__ void __launch_bounds__(1024) k_scan() {
    __shared__ int wsum[32];
    int t = threadIdx.x, lane = t & 31, w = t >> 5;
    int base = t * 64;
    int s = 0;
#pragma unroll 8
    for (int j = 0; j < 64; j++) s += g_flag[base + j];
    int v = s;
#pragma unroll
    for (int o = 1; o < 32; o <<= 1) {
        int u = __shfl_up_sync(0xffffffffu, v, o);
        if (lane >= o) v += u;
    }
    if (lane == 31) wsum[w] = v;
    __syncthreads();
    if (w == 0) {
        int x2 = wsum[lane];
#pragma unroll
        for (int o = 1; o < 32; o <<= 1) {
            int u = __shfl_up_sync(0xffffffffu, x2, o);
            if (lane >= o) x2 += u;
        }
        wsum[lane] = x2;
    }
    __syncthreads();
    int excl = v - s + (w ? wsum[w - 1] : 0);
    int idx = excl;
    for (int j = 0; j < 64; j++) {
        int r = base + j;
        if (g_flag[r]) { g_list[idx] = r; g_pos[r] = idx; idx++; }
    }
    if (t == 1023) {
        int tot = excl + s;
        g_cnt[0] = tot;
        g_cnt[1] = (tot + 127) & ~127;
    }
}

// ---- fused prep: rmsnorm | weight converts | remap | flag clear -------------
__global__ void __launch_bounds__(256) k_prep(const float* __restrict__ x,
                                              const float* __restrict__ lnw,
                                              const float* __restrict__ qw,
                                              const float* __restrict__ kw,
                                              const float* __restrict__ vw,
                                              const int* __restrict__ rep) {
    const int b = blockIdx.x, tid = threadIdx.x;

    if (b < PREP_RMS) {
        int ci   = (b * 256 + tid) >> 5;
        int lane = tid & 31;
        int cnt = g_cnt[0], cpad = g_cnt[1];
        if (ci >= cpad) return;
        uint2* hp = reinterpret_cast<uint2*>(g_h + (size_t)ci * HID);
        if (ci >= cnt) {
            uint2 z = make_uint2(0u, 0u);
#pragma unroll
            for (int i = 0; i < 8; i++) hp[lane + i * 32] = z;
            return;
        }
        int row = g_list[ci];
        const float4* xp = reinterpret_cast<const float4*>(x + (size_t)row * HID);
        float4 v[8];
        float ss = 0.f;
#pragma unroll
        for (int i = 0; i < 8; i++) {
            v[i] = xp[lane + i * 32];
            ss += v[i].x * v[i].x + v[i].y * v[i].y + v[i].z * v[i].z + v[i].w * v[i].w;
        }
#pragma unroll
        for (int o = 16; o > 0; o >>= 1) ss += __shfl_xor_sync(0xffffffffu, ss, o);
        float rs = rsqrtf(ss * (1.0f / HID) + EPS);
        const float4* wp = reinterpret_cast<const float4*>(lnw);
#pragma unroll
        for (int i = 0; i < 8; i++) {
            float4 wv = wp[lane + i * 32];
            float4 t = make_float4(v[i].x * rs * wv.x, v[i].y * rs * wv.y,
                                   v[i].z * rs * wv.z, v[i].w * rs * wv.w);
            hp[lane + i * 32] = f4_to_h2x2(t);
        }
    } else if (b < PREP_RMS + PREP_W) {
        int j = b - PREP_RMS;
        int which = j >> 10;
        int i = (j & 1023) * 256 + tid;
        const float* src = (which == 0) ? qw : (which == 1) ? kw : vw;
        __half* dst = (which == 0) ? g_wq : (which == 1) ? g_wk : g_wv;
        float4 v = reinterpret_cast<const float4*>(src)[i];
        reinterpret_cast<uint2*>(dst)[i] = f4_to_h2x2(v);
    } else if (b < PREP_RMS + PREP_W + PREP_RMAP) {
        int i = (b - PREP_RMS - PREP_W) * 256 + tid;
        g_rep2[i] = g_pos[rep[i]];
    } else {
        int i = (b - PREP_RMS - PREP_W - PREP_RMAP) * 256 + tid;
        reinterpret_cast<int*>(g_flag)[i] = 0;
    }
}

// ---- GEMM-Q (+ fused y->fp16 conversion): 256 thr, 32x64 warp, 3-stage ------
__global__ void __launch_bounds__(256, 1) k_gemm_q(const float* __restrict__ qb,
                                                   const float* __restrict__ y) {
    const int n0 = blockIdx.x * 128, m0 = blockIdx.y * 128;
    const int tid = threadIdx.x;
    const int cid = blockIdx.y * 8 + blockIdx.x;
    const float4* yf4 = reinterpret_cast<const float4*>(y);
    uint2* yh2 = reinterpret_cast<uint2*>(g_yb);
    const size_t ybase = (size_t)cid * 4096 + tid;

    if (m0 >= g_cnt[1]) {                   // inactive tile: convert slice, exit
#pragma unroll 4
        for (int ci = 0; ci < NCH; ci++)
            yh2[ybase + ci * 256] = f4_to_h2x2(yf4[ybase + ci * 256]);
        return;
    }

    extern __shared__ char smem[];
    const int w = tid >> 5, l = tid & 31;
    const int wr = w >> 1, wc = w & 1;
    float* qb_s = reinterpret_cast<float*>(smem);
    uint32_t sb = smem_u32(smem) + 512;

    if (tid < 128) qb_s[tid] = qb[n0 + tid];
    load_tile(sb,                       g_h,  m0, 0);
    load_tile(sb + TILE_B,              g_wq, n0, 0);
    CP_COMMIT();
    load_tile(sb + 2 * TILE_B,          g_h,  m0, KC);
    load_tile(sb + 2 * TILE_B + TILE_B, g_wq, n0, KC);
    CP_COMMIT();

    float4 yv = yf4[ybase];

    float acc[2][8][4];
#pragma unroll
    for (int mt = 0; mt < 2; mt++)
#pragma unroll
        for (int nt = 0; nt < 8; nt++)
#pragma unroll
            for (int i = 0; i < 4; i++) acc[mt][nt][i] = 0.f;

    const int a_row = wr * 32 + (l & 7) + ((l >> 3) & 1) * 8;
    const int a_kb  = (l >> 4) * 16;
    const int b_row = wc * 64 + ((l >> 4) & 1) * 8 + (l & 7);
    const int b_kb  = ((l >> 3) & 1) * 16;

    for (int ci = 0; ci < NCH; ci++) {
        CP_WAIT(1);
        __syncthreads();
        if (ci + 2 < NCH) {
            uint32_t tb = sb + (uint32_t)((ci + 2) % STG) * (2 * TILE_B);
            load_tile(tb,          g_h,  m0, (ci + 2) * KC);
            load_tile(tb + TILE_B, g_wq, n0, (ci + 2) * KC);
        }
        CP_COMMIT();

        {   // y conversion, pipelined one chunk ahead
            float4 ynext;
            if (ci + 1 < NCH) ynext = yf4[ybase + (size_t)(ci + 1) * 256];
            yh2[ybase + (size_t)ci * 256] = f4_to_h2x2(yv);
            yv = ynext;
        }

        uint32_t sA = sb + (uint32_t)(ci % STG) * (2 * TILE_B);
        uint32_t sB = sA + TILE_B;
#pragma unroll
        for (int ks = 0; ks < 4; ks++) {
            uint32_t af[2][4], bf[4][4];
#pragma unroll
            for (int mt = 0; mt < 2; mt++)
                ldm_x4(af[mt], sA + (a_row + mt * 16) * (TPAD * 2) + ks * 32 + a_kb);
#pragma unroll
            for (int np = 0; np < 4; np++)
                ldm_x4(bf[np], sB + (b_row + np * 16) * (TPAD * 2) + ks * 32 + b_kb);
#pragma unroll
            for (int mt = 0; mt < 2; mt++)
#pragma unroll
                for (int np = 0; np < 4; np++) {
                    mma_h32(acc[mt][2 * np],     af[mt], bf[np]);
                    mma_h32(acc[mt][2 * np + 1], af[mt], bf[np] + 2);
                }
        }
    }

#pragma unroll
    for (int mt = 0; mt < 2; mt++)
#pragma unroll
        for (int nt = 0; nt < 8; nt++) {
            int col = wc * 64 + nt * 8 + 2 * (l & 3);
            float b0 = qb_s[col], b1 = qb_s[col + 1];
            int r0 = m0 + wr * 32 + mt * 16 + (l >> 2);
            __half2 p0 = __floats2half2_rn(acc[mt][nt][0] + b0, acc[mt][nt][1] + b1);
            __half2 p1 = __floats2half2_rn(acc[mt][nt][2] + b0, acc[mt][nt][3] + b1);
            *reinterpret_cast<__half2*>(g_xq + (size_t)r0 * HID + n0 + col) = p0;
            *reinterpret_cast<__half2*>(g_xq + (size_t)(r0 + 8) * HID + n0 + col) = p1;
        }
}

// ------ persistent fused GEMM-KV + attention epilogue: cross-tile pipe -------
__global__ void __launch_bounds__(256, 1) k_gemm_kv(const float* __restrict__ x,
                                                    const float* __restrict__ kb,
                                                    const float* __restrict__ vb,
                                                    float* __restrict__ out) {
    extern __shared__ char smem[];
    const int tid = threadIdx.x, w = tid >> 5, l = tid & 31;
    const int wr = w >> 1, wc = w & 1;
    const int bid = blockIdx.x, GR = gridDim.x;
    uint32_t sb = smem_u32(smem);

    const int a_row = wr * 32 + (l & 7) + ((l >> 3) & 1) * 8;
    const int a_kb  = (l >> 4) * 16;
    const int b_row = wc * 64 + ((l >> 4) & 1) * 8 + (l & 7);
    const int b_kb  = ((l >> 3) & 1) * 16;

    // prologue: prefetch chunks 0,1 of first tile
    {
        int m0 = (bid >> 3) * 128, n0 = (bid & 7) * 128;
        load_tile(sb,              g_yb, m0, 0);
        load_tile(sb + TILE_B,     g_wk, n0, 0);
        load_tile(sb + 2 * TILE_B, g_wv, n0, 0);
        CP_COMMIT();
        load_tile(sb + 3 * TILE_B,              g_yb, m0, KC);
        load_tile(sb + 3 * TILE_B + TILE_B,     g_wk, n0, KC);
        load_tile(sb + 3 * TILE_B + 2 * TILE_B, g_wv, n0, KC);
        CP_COMMIT();
    }

    int gc = 0;                                 // global chunk counter
    for (int tile = bid; tile < NTILES; tile += GR) {
        const int m0 = (tile >> 3) * 128, n0 = (tile & 7) * 128;

        float accK[2][8][4], accV[2][8][4];
#pragma unroll
        for (int mt = 0; mt < 2; mt++)
#pragma unroll
            for (int nt = 0; nt < 8; nt++)
#pragma unroll
                for (int i = 0; i < 4; i++) { accK[mt][nt][i] = 0.f; accV[mt][nt][i] = 0.f; }

        for (int ci = 0; ci < NCH; ci++, gc++) {
            CP_WAIT(1);
            __syncthreads();
            {   // prefetch chunk position gc+2 (may wrap into next tile)
                int ci2 = ci + 2, t2 = tile;
                if (ci2 >= NCH) { ci2 -= NCH; t2 += GR; }
                if (t2 < NTILES) {
                    int m2 = (t2 >> 3) * 128, n2 = (t2 & 7) * 128;
                    uint32_t tb = sb + (uint32_t)((gc + 2) % STG) * (3 * TILE_B);
                    load_tile(tb,              g_yb, m2, ci2 * KC);
                    load_tile(tb + TILE_B,     g_wk, n2, ci2 * KC);
                    load_tile(tb + 2 * TILE_B, g_wv, n2, ci2 * KC);
                }
                CP_COMMIT();                    // always commit
            }

            uint32_t sA  = sb + (uint32_t)(gc % STG) * (3 * TILE_B);
            uint32_t sBk = sA + TILE_B;
            uint32_t sBv = sA + 2 * TILE_B;
#pragma unroll
            for (int ks = 0; ks < 4; ks++) {
                uint32_t af[2][4], bk[4][4], bv[4][4];
#pragma unroll
                for (int mt = 0; mt < 2; mt++)
                    ldm_x4(af[mt], sA + (a_row + mt * 16) * (TPAD * 2) + ks * 32 + a_kb);
#pragma unroll
                for (int np = 0; np < 4; np++) {
                    uint32_t off = (b_row + np * 16) * (TPAD * 2) + ks * 32 + b_kb;
                    ldm_x4(bk[np], sBk + off);
                    ldm_x4(bv[np], sBv + off);
                }
#pragma unroll
                for (int mt = 0; mt < 2; mt++)
#pragma unroll
                    for (int np = 0; np < 4; np++) {
                        mma_h32(accK[mt][2 * np],     af[mt], bk[np]);
                        mma_h32(accK[mt][2 * np + 1], af[mt], bk[np] + 2);
                        mma_h32(accV[mt][2 * np],     af[mt], bv[np]);
                        mma_h32(accV[mt][2 * np + 1], af[mt], bv[np] + 2);
                    }
            }
        }

        // ---- attention epilogue (no smem; overlaps next tile's loads) -------
        float dp[4] = {0, 0, 0, 0}, qn2[4] = {0, 0, 0, 0}, kn2[4] = {0, 0, 0, 0};
        int rbase = m0 + wr * 32 + (l >> 2);
        int qrow[4];
#pragma unroll
        for (int p = 0; p < 4; p++) qrow[p] = g_rep2[rbase + p * 8];

#pragma unroll
        for (int mt = 0; mt < 2; mt++)
#pragma unroll
            for (int nt = 0; nt < 8; nt++) {
                int col = wc * 64 + nt * 8 + 2 * (l & 3);
                float kb0 = kb[n0 + col], kb1 = kb[n0 + col + 1];
#pragma unroll
                for (int h = 0; h < 2; h++) {
                    int p = mt * 2 + h;
                    float k0 = accK[mt][nt][2 * h]     + kb0;
                    float k1 = accK[mt][nt][2 * h + 1] + kb1;
                    float2 qf = __half22float2(*reinterpret_cast<const __half2*>(
                        g_xq + (size_t)qrow[p] * HID + n0 + col));
                    dp[p]  += qf.x * k0 + qf.y * k1;
                    qn2[p] += qf.x * qf.x + qf.y * qf.y;
                    kn2[p] += k0 * k0 + k1 * k1;
                }
            }
#pragma unroll
        for (int o = 1; o <= 2; o <<= 1)
#pragma unroll
            for (int p = 0; p < 4; p++) {
                dp[p]  += __shfl_xor_sync(0xffffffffu, dp[p],  o);
                qn2[p] += __shfl_xor_sync(0xffffffffu, qn2[p], o);
                kn2[p] += __shfl_xor_sync(0xffffffffu, kn2[p], o);
            }
        float att[4];
#pragma unroll
        for (int p = 0; p < 4; p++)
            att[p] = dp[p] / (fmaxf(sqrtf(qn2[p]), EPS) * fmaxf(sqrtf(kn2[p]), EPS));

#pragma unroll
        for (int mt = 0; mt < 2; mt++)
#pragma unroll
            for (int nt = 0; nt < 8; nt++) {
                int col = wc * 64 + nt * 8 + 2 * (l & 3);
                float vb0 = vb[n0 + col], vb1 = vb[n0 + col + 1];
#pragma unroll
                for (int h = 0; h < 2; h++) {
                    int p = mt * 2 + h;
                    int grow = rbase + mt * 16 + h * 8;
                    const float2 xv = *reinterpret_cast<const float2*>(
                        x + (size_t)grow * HID + n0 + col);
                    float2 o;
                    o.x = xv.x + (accV[mt][nt][2 * h]     + vb0) * att[p];
                    o.y = xv.y + (accV[mt][nt][2 * h + 1] + vb1) * att[p];
                    *reinterpret_cast<float2*>(out + (size_t)grow * HID + n0 + col) = o;
                }
            }
    }
}

// ---------------- launch -----------------------------------------------------
extern "C" void kernel_launch(void* const* d_in, const int* in_sizes, int n_in,
                              void* d_out, int out_size) {
    const float* x    = (const float*)d_in[0];
    const float* y    = (const float*)d_in[1];
    const int*   rep  = (const int*)d_in[2];
    const float* ln_w = (const float*)d_in[3];
    const float* q_w  = (const float*)d_in[4];
    const float* q_b  = (const float*)d_in[5];
    const float* k_w  = (const float*)d_in[6];
    const float* k_b  = (const float*)d_in[7];
    const float* v_w  = (const float*)d_in[8];
    const float* v_b  = (const float*)d_in[9];
    float* out = (float*)d_out;

    cudaFuncSetAttribute(k_gemm_q,  cudaFuncAttributeMaxDynamicSharedMemorySize, SMEM_Q);
    cudaFuncSetAttribute(k_gemm_kv, cudaFuncAttributeMaxDynamicSharedMemorySize, SMEM_KV);

    k_mark<<<64, 1024>>>(rep);
    k_scan<<<1, 1024>>>();
    k_prep<<<PREP_GRID, 256>>>(x, ln_w, q_w, k_w, v_w, rep);

    dim3 gq(HID / 128, NROWS / 128);    // (8, 512)
    k_gemm_q<<<gq, 256, SMEM_Q>>>(q_b, y);
    k_gemm_kv<<<PGRID, 256, SMEM_KV>>>(x, k_b, v_b, out);
}

// round 14
// speedup vs baseline: 1.0130x; 1.0130x over previous
#include <cuda_runtime.h>
#include <cuda_fp16.h>
#include <cstdint>

// ============================================================================
// ResAttentionBlock (ptxas target sm_103 rejects tcgen05 -> legacy mma.sync).
// R14: R11 structure (best: 1378.8us). Q kernel change only: y->fp16
//      conversion slices assigned ONLY to active (heavy) CTAs (~2 rows/chunk,
//      loads early / stores after the chunk's HMMAs), inactive CTAs exit
//      immediately -> deletes ~10 trailing memory-only waves.
// ============================================================================

#define EPS 1e-6f
constexpr int NROWS = 65536;
constexpr int HID   = 1024;
constexpr int KC    = 64;              // k-chunk (elements)
constexpr int NCH   = HID / KC;        // 16
constexpr int TPAD  = 72;              // padded row stride in fp16 elems (144B)
constexpr int TILE_B = 128 * TPAD * 2; // one 128x64 fp16 tile = 18432 B
constexpr int STG   = 3;               // pipeline stages

constexpr int SMEM_Q  = 512  + STG * 2 * TILE_B;   // 111104
constexpr int SMEM_KV = 1024 + STG * 3 * TILE_B;   // 166912

// k_prep grid partition
constexpr int PREP_RMS  = 8192;
constexpr int PREP_W    = 3072;
constexpr int PREP_RMAP = 256;
constexpr int PREP_FLAG = 64;
constexpr int PREP_GRID = PREP_RMS + PREP_W + PREP_RMAP + PREP_FLAG;

// ---------------- scratch (device globals; no allocation allowed) -----------
__device__ __align__(16) __half g_h [67108864];
__device__ __align__(16) __half g_yb[67108864];
__device__ __align__(16) __half g_xq[67108864];
__device__ __align__(16) __half g_wq[1048576];
__device__ __align__(16) __half g_wk[1048576];
__device__ __align__(16) __half g_wv[1048576];
__device__ __align__(16) int g_list[NROWS];
__device__ __align__(16) int g_pos [NROWS];
__device__ __align__(16) int g_rep2[NROWS];
__device__ __align__(16) unsigned char g_flag[NROWS];   // BSS zero-initialized
__device__ int g_cnt[2];

// ---------------- helpers ----------------------------------------------------
__device__ __forceinline__ uint32_t smem_u32(const void* p) {
    uint32_t a;
    asm("{ .reg .u64 t; cvta.to.shared.u64 t, %1; cvt.u32.u64 %0, t; }" : "=r"(a) : "l"(p));
    return a;
}
__device__ __forceinline__ void cp_async16(uint32_t dst, const void* src) {
    asm volatile("cp.async.cg.shared.global [%0], [%1], 16;" :: "r"(dst), "l"(src) : "memory");
}
#define CP_COMMIT() asm volatile("cp.async.commit_group;" ::: "memory")
#define CP_WAIT(n)  asm volatile("cp.async.wait_group %0;" :: "n"(n) : "memory")

__device__ __forceinline__ void ldm_x4(uint32_t* r, uint32_t addr) {
    asm volatile("ldmatrix.sync.aligned.m8n8.x4.shared.b16 {%0,%1,%2,%3}, [%4];"
                 : "=r"(r[0]), "=r"(r[1]), "=r"(r[2]), "=r"(r[3]) : "r"(addr));
}
__device__ __forceinline__ void mma_h32(float* d, const uint32_t* a, const uint32_t* b) {
    asm volatile(
        "mma.sync.aligned.m16n8k16.row.col.f32.f16.f16.f32 "
        "{%0,%1,%2,%3}, {%4,%5,%6,%7}, {%8,%9}, {%0,%1,%2,%3};"
        : "+f"(d[0]), "+f"(d[1]), "+f"(d[2]), "+f"(d[3])
        : "r"(a[0]), "r"(a[1]), "r"(a[2]), "r"(a[3]), "r"(b[0]), "r"(b[1]));
}
__device__ __forceinline__ uint2 f4_to_h2x2(float4 v) {
    __half2 p0 = __floats2half2_rn(v.x, v.y);
    __half2 p1 = __floats2half2_rn(v.z, v.w);
    uint2 s;
    s.x = *reinterpret_cast<uint32_t*>(&p0);
    s.y = *reinterpret_cast<uint32_t*>(&p1);
    return s;
}

// Load one 128-row x 64-col fp16 tile into padded smem (stride 144B). 256 thr.
__device__ __forceinline__ void load_tile(uint32_t sbase, const __half* __restrict__ g,
                                          int row0, int col0) {
    const int tid = threadIdx.x;
#pragma unroll
    for (int k = 0; k < 4; k++) {
        int u = tid + k * 256;
        int r = u >> 3, c = u & 7;
        cp_async16(sbase + r * (TPAD * 2) + c * 16,
                   g + (size_t)(row0 + r) * HID + col0 + c * 8);
    }
}

// ---------------- compaction kernels -----------------------------------------
__global__ void __launch_bounds__(1024) k_mark(const int* __restrict__ rep) {
    g_flag[rep[blockIdx.x * 1024 + threadIdx.x]] = 1;
}
__global__ void __launch_bounds__(1024) k_scan() {
    __shared__ int wsum[32];
    int t = threadIdx.x, lane = t & 31, w = t >> 5;
    int base = t * 64;
    int s = 0;
#pragma unroll 8
    for (int j = 0; j < 64; j++) s += g_flag[base + j];
    int v = s;
#pragma unroll
    for (int o = 1; o < 32; o <<= 1) {
        int u = __shfl_up_sync(0xffffffffu, v, o);
        if (lane >= o) v += u;
    }
    if (lane == 31) wsum[w] = v;
    __syncthreads();
    if (w == 0) {
        int x2 = wsum[lane];
#pragma unroll
        for (int o = 1; o < 32; o <<= 1) {
            int u = __shfl_up_sync(0xffffffffu, x2, o);
            if (lane >= o) x2 += u;
        }
        wsum[lane] = x2;
    }
    __syncthreads();
    int excl = v - s + (w ? wsum[w - 1] : 0);
    int idx = excl;
    for (int j = 0; j < 64; j++) {
        int r = base + j;
        if (g_flag[r]) { g_list[idx] = r; g_pos[r] = idx; idx++; }
    }
    if (t == 1023) {
        int tot = excl + s;
        g_cnt[0] = tot;
        g_cnt[1] = (tot + 127) & ~127;
    }
}

// ---- fused prep: rmsnorm | weight converts | remap | flag clear -------------
__global__ void __launch_bounds__(256) k_prep(const float* __restrict__ x,
                                              const float* __restrict__ lnw,
                                              const float* __restrict__ qw,
                                              const float* __restrict__ kw,
                                              const float* __restrict__ vw,
                                              const int* __restrict__ rep) {
    const int b = blockIdx.x, tid = threadIdx.x;

    if (b < PREP_RMS) {
        int ci   = (b * 256 + tid) >> 5;
        int lane = tid & 31;
        int cnt = g_cnt[0], cpad = g_cnt[1];
        if (ci >= cpad) return;
        uint2* hp = reinterpret_cast<uint2*>(g_h + (size_t)ci * HID);
        if (ci >= cnt) {
            uint2 z = make_uint2(0u, 0u);
#pragma unroll
            for (int i = 0; i < 8; i++) hp[lane + i * 32] = z;
            return;
        }
        int row = g_list[ci];
        const float4* xp = reinterpret_cast<const float4*>(x + (size_t)row * HID);
        float4 v[8];
        float ss = 0.f;
#pragma unroll
        for (int i = 0; i < 8; i++) {
            v[i] = xp[lane + i * 32];
            ss += v[i].x * v[i].x + v[i].y * v[i].y + v[i].z * v[i].z + v[i].w * v[i].w;
        }
#pragma unroll
        for (int o = 16; o > 0; o >>= 1) ss += __shfl_xor_sync(0xffffffffu, ss, o);
        float rs = rsqrtf(ss * (1.0f / HID) + EPS);
        const float4* wp = reinterpret_cast<const float4*>(lnw);
#pragma unroll
        for (int i = 0; i < 8; i++) {
            float4 wv = wp[lane + i * 32];
            float4 t = make_float4(v[i].x * rs * wv.x, v[i].y * rs * wv.y,
                                   v[i].z * rs * wv.z, v[i].w * rs * wv.w);
            hp[lane + i * 32] = f4_to_h2x2(t);
        }
    } else if (b < PREP_RMS + PREP_W) {
        int j = b - PREP_RMS;
        int which = j >> 10;
        int i = (j & 1023) * 256 + tid;
        const float* src = (which == 0) ? qw : (which == 1) ? kw : vw;
        __half* dst = (which == 0) ? g_wq : (which == 1) ? g_wk : g_wv;
        float4 v = reinterpret_cast<const float4*>(src)[i];
        reinterpret_cast<uint2*>(dst)[i] = f4_to_h2x2(v);
    } else if (b < PREP_RMS + PREP_W + PREP_RMAP) {
        int i = (b - PREP_RMS - PREP_W) * 256 + tid;
        g_rep2[i] = g_pos[rep[i]];
    } else {
        int i = (b - PREP_RMS - PREP_W - PREP_RMAP) * 256 + tid;
        reinterpret_cast<int*>(g_flag)[i] = 0;
    }
}

// ---- GEMM-Q (+ fused y->fp16 conversion over ACTIVE CTAs only) --------------
__global__ void __launch_bounds__(256, 1) k_gemm_q(const float* __restrict__ qb,
                                                   const float* __restrict__ y) {
    const int n0 = blockIdx.x * 128, m0 = blockIdx.y * 128;
    if (m0 >= g_cnt[1]) return;             // inactive tile: exit immediately
    const int tid = threadIdx.x;

    // conversion slice: active CTAs are exactly cid in [0, nact)
    const int cid  = blockIdx.y * 8 + blockIdx.x;
    const int nact = (g_cnt[1] >> 7) * 8;
    const int R    = (NROWS + nact - 1) / nact;
    const int rs0  = cid * R;
    const int rs1  = min(rs0 + R, NROWS);
    const int nr   = rs1 - rs0;             // rows this CTA converts (~26)
    const float4* yf4 = reinterpret_cast<const float4*>(y);
    uint2* yh2 = reinterpret_cast<uint2*>(g_yb);

    extern __shared__ char smem[];
    const int w = tid >> 5, l = tid & 31;
    const int wr = w >> 1, wc = w & 1;
    float* qb_s = reinterpret_cast<float*>(smem);
    uint32_t sb = smem_u32(smem) + 512;

    if (tid < 128) qb_s[tid] = qb[n0 + tid];
    load_tile(sb,                       g_h,  m0, 0);
    load_tile(sb + TILE_B,              g_wq, n0, 0);
    CP_COMMIT();
    load_tile(sb + 2 * TILE_B,          g_h,  m0, KC);
    load_tile(sb + 2 * TILE_B + TILE_B, g_wq, n0, KC);
    CP_COMMIT();

    float acc[2][8][4];
#pragma unroll
    for (int mt = 0; mt < 2; mt++)
#pragma unroll
        for (int nt = 0; nt < 8; nt++)
#pragma unroll
            for (int i = 0; i < 4; i++) acc[mt][nt][i] = 0.f;

    const int a_row = wr * 32 + (l & 7) + ((l >> 3) & 1) * 8;
    const int a_kb  = (l >> 4) * 16;
    const int b_row = wc * 64 + ((l >> 4) & 1) * 8 + (l & 7);
    const int b_kb  = ((l >> 3) & 1) * 16;

    for (int ci = 0; ci < NCH; ci++) {
        CP_WAIT(1);
        __syncthreads();
        if (ci + 2 < NCH) {
            uint32_t tb = sb + (uint32_t)((ci + 2) % STG) * (2 * TILE_B);
            load_tile(tb,          g_h,  m0, (ci + 2) * KC);
            load_tile(tb + TILE_B, g_wq, n0, (ci + 2) * KC);
        }
        CP_COMMIT();

        // conversion rows for this chunk: [ra, rb) of the CTA slice.
        // Loads issued here; stores after the chunk's HMMAs (latency hidden).
        const int ra = rs0 + (ci * nr) / NCH;
        const int rb = rs0 + ((ci + 1) * nr) / NCH;
        const int nrow = rb - ra;               // ~2 in practice
        float4 t0, t1;
        if (nrow > 0) t0 = yf4[(size_t)ra * 256 + tid];
        if (nrow > 1) t1 = yf4[(size_t)(ra + 1) * 256 + tid];

        uint32_t sA = sb + (uint32_t)(ci % STG) * (2 * TILE_B);
        uint32_t sB = sA + TILE_B;
#pragma unroll
        for (int ks = 0; ks < 4; ks++) {
            uint32_t af[2][4], bf[4][4];
#pragma unroll
            for (int mt = 0; mt < 2; mt++)
                ldm_x4(af[mt], sA + (a_row + mt * 16) * (TPAD * 2) + ks * 32 + a_kb);
#pragma unroll
            for (int np = 0; np < 4; np++)
                ldm_x4(bf[np], sB + (b_row + np * 16) * (TPAD * 2) + ks * 32 + b_kb);
#pragma unroll
            for (int mt = 0; mt < 2; mt++)
#pragma unroll
                for (int np = 0; np < 4; np++) {
                    mma_h32(acc[mt][2 * np],     af[mt], bf[np]);
                    mma_h32(acc[mt][2 * np + 1], af[mt], bf[np] + 2);
                }
        }

        if (nrow > 0) yh2[(size_t)ra * 256 + tid] = f4_to_h2x2(t0);
        if (nrow > 1) yh2[(size_t)(ra + 1) * 256 + tid] = f4_to_h2x2(t1);
        for (int r = ra + 2; r < rb; r++)       // never taken in practice
            yh2[(size_t)r * 256 + tid] = f4_to_h2x2(yf4[(size_t)r * 256 + tid]);
    }

#pragma unroll
    for (int mt = 0; mt < 2; mt++)
#pragma unroll
        for (int nt = 0; nt < 8; nt++) {
            int col = wc * 64 + nt * 8 + 2 * (l & 3);
            float b0 = qb_s[col], b1 = qb_s[col + 1];
            int r0 = m0 + wr * 32 + mt * 16 + (l >> 2);
            __half2 p0 = __floats2half2_rn(acc[mt][nt][0] + b0, acc[mt][nt][1] + b1);
            __half2 p1 = __floats2half2_rn(acc[mt][nt][2] + b0, acc[mt][nt][3] + b1);
            *reinterpret_cast<__half2*>(g_xq + (size_t)r0 * HID + n0 + col) = p0;
            *reinterpret_cast<__half2*>(g_xq + (size_t)(r0 + 8) * HID + n0 + col) = p1;
        }
}

// ---------------- fused GEMM-KV + attention epilogue: 3-stage pipe -----------
__global__ void __launch_bounds__(256, 1) k_gemm_kv(const float* __restrict__ x,
                                                    const float* __restrict__ kb,
                                                    const float* __restrict__ vb,
                                                    float* __restrict__ out) {
    extern __shared__ char smem[];
    const int tid = threadIdx.x, w = tid >> 5, l = tid & 31;
    const int wr = w >> 1, wc = w & 1;
    const int n0 = blockIdx.x * 128, m0 = blockIdx.y * 128;
    float* kb_s = reinterpret_cast<float*>(smem);
    float* vb_s = kb_s + 128;
    uint32_t sb = smem_u32(smem) + 1024;

    if (tid < 128) { kb_s[tid] = kb[n0 + tid]; vb_s[tid] = vb[n0 + tid]; }
    load_tile(sb,                           g_yb, m0, 0);
    load_tile(sb + TILE_B,                  g_wk, n0, 0);
    load_tile(sb + 2 * TILE_B,              g_wv, n0, 0);
    CP_COMMIT();
    load_tile(sb + 3 * TILE_B,              g_yb, m0, KC);
    load_tile(sb + 3 * TILE_B + TILE_B,     g_wk, n0, KC);
    load_tile(sb + 3 * TILE_B + 2 * TILE_B, g_wv, n0, KC);
    CP_COMMIT();

    float accK[2][8][4], accV[2][8][4];
#pragma unroll
    for (int mt = 0; mt < 2; mt++)
#pragma unroll
        for (int nt = 0; nt < 8; nt++)
#pragma unroll
            for (int i = 0; i < 4; i++) { accK[mt][nt][i] = 0.f; accV[mt][nt][i] = 0.f; }

    const int a_row = wr * 32 + (l & 7) + ((l >> 3) & 1) * 8;
    const int a_kb  = (l >> 4) * 16;
    const int b_row = wc * 64 + ((l >> 4) & 1) * 8 + (l & 7);
    const int b_kb  = ((l >> 3) & 1) * 16;

    for (int ci = 0; ci < NCH; ci++) {
        CP_WAIT(1);
        __syncthreads();
        if (ci + 2 < NCH) {
            uint32_t tb = sb + (uint32_t)((ci + 2) % STG) * (3 * TILE_B);
            load_tile(tb,              g_yb, m0, (ci + 2) * KC);
            load_tile(tb + TILE_B,     g_wk, n0, (ci + 2) * KC);
            load_tile(tb + 2 * TILE_B, g_wv, n0, (ci + 2) * KC);
        }
        CP_COMMIT();

        uint32_t sA  = sb + (uint32_t)(ci % STG) * (3 * TILE_B);
        uint32_t sBk = sA + TILE_B;
        uint32_t sBv = sA + 2 * TILE_B;
#pragma unroll
        for (int ks = 0; ks < 4; ks++) {
            uint32_t af[2][4], bk[4][4], bv[4][4];
#pragma unroll
            for (int mt = 0; mt < 2; mt++)
                ldm_x4(af[mt], sA + (a_row + mt * 16) * (TPAD * 2) + ks * 32 + a_kb);
#pragma unroll
            for (int np = 0; np < 4; np++) {
                uint32_t off = (b_row + np * 16) * (TPAD * 2) + ks * 32 + b_kb;
                ldm_x4(bk[np], sBk + off);
                ldm_x4(bv[np], sBv + off);
            }
#pragma unroll
            for (int mt = 0; mt < 2; mt++)
#pragma unroll
                for (int np = 0; np < 4; np++) {
                    mma_h32(accK[mt][2 * np],     af[mt], bk[np]);
                    mma_h32(accK[mt][2 * np + 1], af[mt], bk[np] + 2);
                    mma_h32(accV[mt][2 * np],     af[mt], bv[np]);
                    mma_h32(accV[mt][2 * np + 1], af[mt], bv[np] + 2);
                }
        }
    }

    // ---- attention epilogue: warp owns rows wr*32..+31, head cols wc*64..+63
    float dp[4] = {0, 0, 0, 0}, qn2[4] = {0, 0, 0, 0}, kn2[4] = {0, 0, 0, 0};
    int rbase = m0 + wr * 32 + (l >> 2);
    int qrow[4];
#pragma unroll
    for (int p = 0; p < 4; p++) qrow[p] = g_rep2[rbase + p * 8];

#pragma unroll
    for (int mt = 0; mt < 2; mt++)
#pragma unroll
        for (int nt = 0; nt < 8; nt++) {
            int col = wc * 64 + nt * 8 + 2 * (l & 3);
            float kb0 = kb_s[col], kb1 = kb_s[col + 1];
#pragma unroll
            for (int h = 0; h < 2; h++) {
                int p = mt * 2 + h;
                float k0 = accK[mt][nt][2 * h]     + kb0;
                float k1 = accK[mt][nt][2 * h + 1] + kb1;
                float2 qf = __half22float2(*reinterpret_cast<const __half2*>(
                    g_xq + (size_t)qrow[p] * HID + n0 + col));
                dp[p]  += qf.x * k0 + qf.y * k1;
                qn2[p] += qf.x * qf.x + qf.y * qf.y;
                kn2[p] += k0 * k0 + k1 * k1;
            }
        }
#pragma unroll
    for (int o = 1; o <= 2; o <<= 1)
#pragma unroll
        for (int p = 0; p < 4; p++) {
            dp[p]  += __shfl_xor_sync(0xffffffffu, dp[p],  o);
            qn2[p] += __shfl_xor_sync(0xffffffffu, qn2[p], o);
            kn2[p] += __shfl_xor_sync(0xffffffffu, kn2[p], o);
        }
    float att[4];
#pragma unroll
    for (int p = 0; p < 4; p++)
        att[p] = dp[p] / (fmaxf(sqrtf(qn2[p]), EPS) * fmaxf(sqrtf(kn2[p]), EPS));

#pragma unroll
    for (int mt = 0; mt < 2; mt++)
#pragma unroll
        for (int nt = 0; nt < 8; nt++) {
            int col = wc * 64 + nt * 8 + 2 * (l & 3);
            float vb0 = vb_s[col], vb1 = vb_s[col + 1];
#pragma unroll
            for (int h = 0; h < 2; h++) {
                int p = mt * 2 + h;
                int grow = rbase + mt * 16 + h * 8;
                const float2 xv = *reinterpret_cast<const float2*>(
                    x + (size_t)grow * HID + n0 + col);
                float2 o;
                o.x = xv.x + (accV[mt][nt][2 * h]     + vb0) * att[p];
                o.y = xv.y + (accV[mt][nt][2 * h + 1] + vb1) * att[p];
                *reinterpret_cast<float2*>(out + (size_t)grow * HID + n0 + col) = o;
            }
        }
}

// ---------------- launch -----------------------------------------------------
extern "C" void kernel_launch(void* const* d_in, const int* in_sizes, int n_in,
                              void* d_out, int out_size) {
    const float* x    = (const float*)d_in[0];
    const float* y    = (const float*)d_in[1];
    const int*   rep  = (const int*)d_in[2];
    const float* ln_w = (const float*)d_in[3];
    const float* q_w  = (const float*)d_in[4];
    const float* q_b  = (const float*)d_in[5];
    const float* k_w  = (const float*)d_in[6];
    const float* k_b  = (const float*)d_in[7];
    const float* v_w  = (const float*)d_in[8];
    const float* v_b  = (const float*)d_in[9];
    float* out = (float*)d_out;

    cudaFuncSetAttribute(k_gemm_q,  cudaFuncAttributeMaxDynamicSharedMemorySize, SMEM_Q);
    cudaFuncSetAttribute(k_gemm_kv, cudaFuncAttributeMaxDynamicSharedMemorySize, SMEM_KV);

    k_mark<<<64, 1024>>>(rep);
    k_scan<<<1, 1024>>>();
    k_prep<<<PREP_GRID, 256>>>(x, ln_w, q_w, k_w, v_w, rep);

    dim3 grid(HID / 128, NROWS / 128);  // (8, 512)
    k_gemm_q<<<grid, 256, SMEM_Q>>>(q_b, y);
    k_gemm_kv<<<grid, 256, SMEM_KV>>>(x, k_b, v_b, out);
}